// round 3
// baseline (speedup 1.0000x reference)
#include <cuda_runtime.h>
#include <cuda_fp16.h>
#include <cstdint>

// ---------------- problem constants ----------------
#define NSAMP   524288
#define DIM0    64
#define WIDTH   128
#define DIMO    16
#define MTILE   128
#define NTILES  (NSAMP / MTILE)   // 4096
#define NTHREADS 256

// ---------------- SMEM layout (bytes) ----------------
// x tile: 128 rows x 72 halfs (64 data + 8 pad) = 144 B/row -> conflict-free ldmatrix
// hidden W: rows padded to 136 halfs = 272 B  (272 = 17*16, banks 0,4,..,28)
// W5:      rows padded to 24 halfs  = 48 B   (48 = 3*16, banks 0,12,24,4,..)
#define XSTR  144
#define WSTR  272
#define W5STR 48
#define SX    0
#define SW0   (SX  + 128 * XSTR)            // 18432
#define SW1   (SW0 + 64  * WSTR)            // 35840
#define SW2   (SW1 + 128 * WSTR)            // 70656
#define SW3   (SW2 + 128 * WSTR)            // 105472
#define SW4   (SW3 + 128 * WSTR)            // 140288
#define SW5   (SW4 + 128 * WSTR)            // 175104
#define SMEM_TOTAL (SW5 + 128 * W5STR)      // 181248

// ---------------- PTX helpers (all plain-sm_103-legal) ----------------
__device__ __forceinline__ uint32_t smem_u32(const void* p) {
    uint32_t a;
    asm("{ .reg .u64 t; cvta.to.shared.u64 t, %1; cvt.u32.u64 %0, t; }"
        : "=r"(a) : "l"(p));
    return a;
}

__device__ __forceinline__ void ldsm_x4(uint32_t* r, uint32_t addr) {
    asm volatile("ldmatrix.sync.aligned.m8n8.x4.shared.b16 {%0,%1,%2,%3}, [%4];"
                 : "=r"(r[0]), "=r"(r[1]), "=r"(r[2]), "=r"(r[3]) : "r"(addr));
}
__device__ __forceinline__ void ldsm_x4t(uint32_t* r, uint32_t addr) {
    asm volatile("ldmatrix.sync.aligned.m8n8.x4.trans.shared.b16 {%0,%1,%2,%3}, [%4];"
                 : "=r"(r[0]), "=r"(r[1]), "=r"(r[2]), "=r"(r[3]) : "r"(addr));
}

// D = A(16x16) * B(16x8) + D, f16 inputs, f32 accum
__device__ __forceinline__ void mma16816(float* c, const uint32_t* a,
                                         uint32_t b0, uint32_t b1) {
    asm volatile(
        "mma.sync.aligned.m16n8k16.row.col.f32.f16.f16.f32 "
        "{%0,%1,%2,%3}, {%4,%5,%6,%7}, {%8,%9}, {%0,%1,%2,%3};"
        : "+f"(c[0]), "+f"(c[1]), "+f"(c[2]), "+f"(c[3])
        : "r"(a[0]), "r"(a[1]), "r"(a[2]), "r"(a[3]), "r"(b0), "r"(b1));
}

__device__ __forceinline__ uint32_t relu_pack(float a, float b) {
    __half2 h = __floats2half2_rn(fmaxf(a, 0.0f), fmaxf(b, 0.0f));
    return *(uint32_t*)&h;
}

// ---------------- kernel ----------------
__global__ void __launch_bounds__(NTHREADS, 1)
mlp_hmma_kernel(const float* __restrict__ x,
                const float* __restrict__ gW0, const float* __restrict__ gW1,
                const float* __restrict__ gW2, const float* __restrict__ gW3,
                const float* __restrict__ gW4, const float* __restrict__ gW5,
                const float* __restrict__ bias,
                float* __restrict__ out) {
    extern __shared__ char smem[];
    const uint32_t sb = smem_u32(smem);
    const int tid  = threadIdx.x;
    const int wid  = tid >> 5;
    const int lane = tid & 31;

    // ---- one-time: all weights -> fp16 SMEM, [K rows x N cols], padded ----
    // W0: 64x128
    for (int i = tid; i < 64 * 128 / 4; i += NTHREADS) {
        int k = i >> 5, n4 = i & 31;
        float4 v = ((const float4*)gW0)[i];
        __half2 h0 = __floats2half2_rn(v.x, v.y), h1 = __floats2half2_rn(v.z, v.w);
        uint2 p = make_uint2(*(uint32_t*)&h0, *(uint32_t*)&h1);
        *(uint2*)(smem + SW0 + k * WSTR + n4 * 8) = p;
    }
    // W1..W4: 128x128
    {
        const float* gws[4] = {gW1, gW2, gW3, gW4};
        const uint32_t so[4] = {SW1, SW2, SW3, SW4};
        for (int w = 0; w < 4; w++) {
            for (int i = tid; i < 128 * 128 / 4; i += NTHREADS) {
                int k = i >> 5, n4 = i & 31;
                float4 v = ((const float4*)gws[w])[i];
                __half2 h0 = __floats2half2_rn(v.x, v.y), h1 = __floats2half2_rn(v.z, v.w);
                uint2 p = make_uint2(*(uint32_t*)&h0, *(uint32_t*)&h1);
                *(uint2*)(smem + so[w] + k * WSTR + n4 * 8) = p;
            }
        }
    }
    // W5: 128x16
    for (int i = tid; i < 128 * 16 / 4; i += NTHREADS) {
        int k = i >> 2, n4 = i & 3;
        float4 v = ((const float4*)gW5)[i];
        __half2 h0 = __floats2half2_rn(v.x, v.y), h1 = __floats2half2_rn(v.z, v.w);
        uint2 p = make_uint2(*(uint32_t*)&h0, *(uint32_t*)&h1);
        *(uint2*)(smem + SW5 + k * W5STR + n4 * 8) = p;
    }

    // per-thread bias (output cols this thread owns)
    const int col0 = (lane & 3) * 2;
    float bz0 = __ldg(bias + col0);
    float bz1 = __ldg(bias + col0 + 1);
    float bz2 = __ldg(bias + 8 + col0);
    float bz3 = __ldg(bias + 9 + col0);

    __syncthreads();

    // per-lane ldmatrix row bases
    const int lrow = (lane & 7) + (((lane >> 3) & 1) << 3);  // 0-15
    const int lhi  = (lane >> 4) & 1;                        // second 8-col/8-k half
    const uint32_t a_base  = sb + SX + (16 * wid + lrow) * XSTR + lhi * 16;
    const uint32_t bw_off  = (uint32_t)lrow * WSTR + lhi * 16;
    const uint32_t b5_off  = (uint32_t)lrow * W5STR + lhi * 16;

    for (int t = blockIdx.x; t < NTILES; t += gridDim.x) {
        // ---- x tile [128 x 64] fp32 -> fp16 padded SMEM ----
        const float4* xg = (const float4*)(x + (size_t)t * MTILE * DIM0);
        #pragma unroll
        for (int i = 0; i < 8; i++) {
            int idx = tid + i * NTHREADS;
            int r = idx >> 4, c4 = idx & 15;
            float4 v = xg[idx];
            __half2 h0 = __floats2half2_rn(v.x, v.y), h1 = __floats2half2_rn(v.z, v.w);
            uint2 p = make_uint2(*(uint32_t*)&h0, *(uint32_t*)&h1);
            *(uint2*)(smem + SX + r * XSTR + c4 * 8) = p;
        }
        __syncthreads();

        // ---- layer 0: [16x64] @ W0[64x128] ----
        uint32_t A[8][4];
        #pragma unroll
        for (int k = 0; k < 4; k++) ldsm_x4(A[k], a_base + k * 32);

        float C[16][4];
        #pragma unroll
        for (int j = 0; j < 16; j++)
            #pragma unroll
            for (int q = 0; q < 4; q++) C[j][q] = 0.0f;

        #pragma unroll
        for (int k = 0; k < 4; k++)
            #pragma unroll
            for (int j = 0; j < 8; j++) {
                uint32_t B[4];
                ldsm_x4t(B, sb + SW0 + bw_off + k * (16 * WSTR) + j * 32);
                mma16816(C[2 * j],     A[k], B[0], B[1]);
                mma16816(C[2 * j + 1], A[k], B[2], B[3]);
            }

        // ---- layers 1..4: register-chained ----
        const uint32_t WS[4] = {SW1, SW2, SW3, SW4};
        #pragma unroll
        for (int l = 0; l < 4; l++) {
            #pragma unroll
            for (int j = 0; j < 8; j++) {
                A[j][0] = relu_pack(C[2 * j][0],     C[2 * j][1]);
                A[j][1] = relu_pack(C[2 * j][2],     C[2 * j][3]);
                A[j][2] = relu_pack(C[2 * j + 1][0], C[2 * j + 1][1]);
                A[j][3] = relu_pack(C[2 * j + 1][2], C[2 * j + 1][3]);
            }
            #pragma unroll
            for (int j = 0; j < 16; j++)
                #pragma unroll
                for (int q = 0; q < 4; q++) C[j][q] = 0.0f;

            #pragma unroll
            for (int k = 0; k < 8; k++)
                #pragma unroll
                for (int j = 0; j < 8; j++) {
                    uint32_t B[4];
                    ldsm_x4t(B, sb + WS[l] + bw_off + k * (16 * WSTR) + j * 32);
                    mma16816(C[2 * j],     A[k], B[0], B[1]);
                    mma16816(C[2 * j + 1], A[k], B[2], B[3]);
                }
        }

        // ---- layer 5: [16x128] @ W5[128x16] ----
        #pragma unroll
        for (int j = 0; j < 8; j++) {
            A[j][0] = relu_pack(C[2 * j][0],     C[2 * j][1]);
            A[j][1] = relu_pack(C[2 * j][2],     C[2 * j][3]);
            A[j][2] = relu_pack(C[2 * j + 1][0], C[2 * j + 1][1]);
            A[j][3] = relu_pack(C[2 * j + 1][2], C[2 * j + 1][3]);
        }
        float C2[2][4];
        #pragma unroll
        for (int j = 0; j < 2; j++)
            #pragma unroll
            for (int q = 0; q < 4; q++) C2[j][q] = 0.0f;

        #pragma unroll
        for (int k = 0; k < 8; k++) {
            uint32_t B[4];
            ldsm_x4t(B, sb + SW5 + b5_off + k * (16 * W5STR));
            mma16816(C2[0], A[k], B[0], B[1]);
            mma16816(C2[1], A[k], B[2], B[3]);
        }

        // ---- store: + bias, fp32 ----
        const int row0 = lane >> 2;
        const size_t g0 = ((size_t)t * MTILE + 16 * wid + row0) * DIMO;
        const size_t g1 = g0 + 8 * DIMO;
        float2 v;
        v.x = C2[0][0] + bz0; v.y = C2[0][1] + bz1;
        *(float2*)(out + g0 + col0) = v;
        v.x = C2[1][0] + bz2; v.y = C2[1][1] + bz3;
        *(float2*)(out + g0 + 8 + col0) = v;
        v.x = C2[0][2] + bz0; v.y = C2[0][3] + bz1;
        *(float2*)(out + g1 + col0) = v;
        v.x = C2[1][2] + bz2; v.y = C2[1][3] + bz3;
        *(float2*)(out + g1 + 8 + col0) = v;

        __syncthreads();   // x tile free for next iteration
    }
}

// ---------------- launch ----------------
extern "C" void kernel_launch(void* const* d_in, const int* in_sizes, int n_in,
                              void* d_out, int out_size) {
    const float* x    = (const float*)d_in[0];
    const float* W0   = (const float*)d_in[1];
    const float* W1   = (const float*)d_in[2];
    const float* W2   = (const float*)d_in[3];
    const float* W3   = (const float*)d_in[4];
    const float* W4   = (const float*)d_in[5];
    const float* W5   = (const float*)d_in[6];
    const float* bias = (const float*)d_in[7];
    float* out = (float*)d_out;

    cudaFuncSetAttribute(mlp_hmma_kernel,
                         cudaFuncAttributeMaxDynamicSharedMemorySize, SMEM_TOTAL);
    int sm = 148;
    cudaDeviceGetAttribute(&sm, cudaDevAttrMultiProcessorCount, 0);
    int grid = sm < NTILES ? sm : NTILES;
    mlp_hmma_kernel<<<grid, NTHREADS, SMEM_TOTAL>>>(x, W0, W1, W2, W3, W4, W5,
                                                    bias, out);
}

// round 4
// speedup vs baseline: 1.0082x; 1.0082x over previous
#include <cuda_runtime.h>
#include <cuda_fp16.h>
#include <cstdint>

// ---------------- problem constants ----------------
#define NSAMP   524288
#define DIM0    64
#define WIDTH   128
#define DIMO    16
#define MTILE   256
#define NTILES  (NSAMP / MTILE)   // 2048
#define NTHREADS 256

// ---------------- SMEM layout (bytes) ----------------
// x tile: 256 rows x 72 halfs (64 data + 8 pad) = 144 B/row -> conflict-free ldmatrix
// hidden W: rows padded to 136 halfs = 272 B
// W5:      rows padded to 24 halfs  = 48 B
#define XSTR  144
#define WSTR  272
#define W5STR 48
#define SX    0
#define SW0   (SX  + 256 * XSTR)            // 36864
#define SW1   (SW0 + 64  * WSTR)            // 54272
#define SW2   (SW1 + 128 * WSTR)            // 89088
#define SW3   (SW2 + 128 * WSTR)            // 123904
#define SW4   (SW3 + 128 * WSTR)            // 158720
#define SW5   (SW4 + 128 * WSTR)            // 193536
#define SMEM_TOTAL (SW5 + 128 * W5STR)      // 199680

// ---------------- PTX helpers (plain-sm_103-legal) ----------------
__device__ __forceinline__ uint32_t smem_u32(const void* p) {
    uint32_t a;
    asm("{ .reg .u64 t; cvta.to.shared.u64 t, %1; cvt.u32.u64 %0, t; }"
        : "=r"(a) : "l"(p));
    return a;
}

__device__ __forceinline__ void ldsm_x4(uint32_t* r, uint32_t addr) {
    asm volatile("ldmatrix.sync.aligned.m8n8.x4.shared.b16 {%0,%1,%2,%3}, [%4];"
                 : "=r"(r[0]), "=r"(r[1]), "=r"(r[2]), "=r"(r[3]) : "r"(addr));
}
__device__ __forceinline__ void ldsm_x4t(uint32_t* r, uint32_t addr) {
    asm volatile("ldmatrix.sync.aligned.m8n8.x4.trans.shared.b16 {%0,%1,%2,%3}, [%4];"
                 : "=r"(r[0]), "=r"(r[1]), "=r"(r[2]), "=r"(r[3]) : "r"(addr));
}

// D = A(16x16) * B(16x8) + D, f16 inputs, f32 accum
__device__ __forceinline__ void mma16816(float* c, const uint32_t* a,
                                         uint32_t b0, uint32_t b1) {
    asm volatile(
        "mma.sync.aligned.m16n8k16.row.col.f32.f16.f16.f32 "
        "{%0,%1,%2,%3}, {%4,%5,%6,%7}, {%8,%9}, {%0,%1,%2,%3};"
        : "+f"(c[0]), "+f"(c[1]), "+f"(c[2]), "+f"(c[3])
        : "r"(a[0]), "r"(a[1]), "r"(a[2]), "r"(a[3]), "r"(b0), "r"(b1));
}

__device__ __forceinline__ uint32_t relu_pack(float a, float b) {
    __half2 h = __floats2half2_rn(fmaxf(a, 0.0f), fmaxf(b, 0.0f));
    return *(uint32_t*)&h;
}

// ---------------- kernel ----------------
__global__ void __launch_bounds__(NTHREADS, 1)
mlp_hmma_kernel(const float* __restrict__ x,
                const float* __restrict__ gW0, const float* __restrict__ gW1,
                const float* __restrict__ gW2, const float* __restrict__ gW3,
                const float* __restrict__ gW4, const float* __restrict__ gW5,
                const float* __restrict__ bias,
                float* __restrict__ out) {
    extern __shared__ char smem[];
    const uint32_t sb = smem_u32(smem);
    const int tid  = threadIdx.x;
    const int wid  = tid >> 5;
    const int lane = tid & 31;

    // ---- one-time: all weights -> fp16 SMEM, [K rows x N cols], padded ----
    for (int i = tid; i < 64 * 128 / 4; i += NTHREADS) {
        int k = i >> 5, n4 = i & 31;
        float4 v = ((const float4*)gW0)[i];
        __half2 h0 = __floats2half2_rn(v.x, v.y), h1 = __floats2half2_rn(v.z, v.w);
        uint2 p = make_uint2(*(uint32_t*)&h0, *(uint32_t*)&h1);
        *(uint2*)(smem + SW0 + k * WSTR + n4 * 8) = p;
    }
    {
        const float* gws[4] = {gW1, gW2, gW3, gW4};
        const uint32_t so[4] = {SW1, SW2, SW3, SW4};
        for (int w = 0; w < 4; w++) {
            for (int i = tid; i < 128 * 128 / 4; i += NTHREADS) {
                int k = i >> 5, n4 = i & 31;
                float4 v = ((const float4*)gws[w])[i];
                __half2 h0 = __floats2half2_rn(v.x, v.y), h1 = __floats2half2_rn(v.z, v.w);
                uint2 p = make_uint2(*(uint32_t*)&h0, *(uint32_t*)&h1);
                *(uint2*)(smem + so[w] + k * WSTR + n4 * 8) = p;
            }
        }
    }
    for (int i = tid; i < 128 * 16 / 4; i += NTHREADS) {
        int k = i >> 2, n4 = i & 3;
        float4 v = ((const float4*)gW5)[i];
        __half2 h0 = __floats2half2_rn(v.x, v.y), h1 = __floats2half2_rn(v.z, v.w);
        uint2 p = make_uint2(*(uint32_t*)&h0, *(uint32_t*)&h1);
        *(uint2*)(smem + SW5 + k * W5STR + n4 * 8) = p;
    }

    // per-thread bias (output cols this thread owns)
    const int col0 = (lane & 3) * 2;
    float bz0 = __ldg(bias + col0);
    float bz1 = __ldg(bias + col0 + 1);
    float bz2 = __ldg(bias + 8 + col0);
    float bz3 = __ldg(bias + 9 + col0);

    __syncthreads();

    // per-lane ldmatrix row bases
    const int lrow = (lane & 7) + (((lane >> 3) & 1) << 3);  // 0-15
    const int lhi  = (lane >> 4) & 1;                        // second 8-col/8-k half
    const uint32_t a_base0 = sb + SX + (32 * wid + lrow) * XSTR + lhi * 16;
    const uint32_t a_base1 = a_base0 + 16 * XSTR;
    const uint32_t bw_off  = (uint32_t)lrow * WSTR + lhi * 16;
    const uint32_t b5_off  = (uint32_t)lrow * W5STR + lhi * 16;

    for (int t = blockIdx.x; t < NTILES; t += gridDim.x) {
        // ---- x tile [256 x 64] fp32 -> fp16 padded SMEM ----
        const float4* xg = (const float4*)(x + (size_t)t * MTILE * DIM0);
        #pragma unroll
        for (int i = 0; i < 16; i++) {
            int idx = tid + i * NTHREADS;
            int r = idx >> 4, c4 = idx & 15;
            float4 v = xg[idx];
            __half2 h0 = __floats2half2_rn(v.x, v.y), h1 = __floats2half2_rn(v.z, v.w);
            uint2 p = make_uint2(*(uint32_t*)&h0, *(uint32_t*)&h1);
            *(uint2*)(smem + SX + r * XSTR + c4 * 8) = p;
        }
        __syncthreads();

        // ---- layer 0: two 16-row blocks [16x64] @ W0[64x128] ----
        uint32_t A[2][8][4];
        #pragma unroll
        for (int k = 0; k < 4; k++) {
            ldsm_x4(A[0][k], a_base0 + k * 32);
            ldsm_x4(A[1][k], a_base1 + k * 32);
        }

        float C[2][16][4];
        #pragma unroll
        for (int b = 0; b < 2; b++)
            #pragma unroll
            for (int j = 0; j < 16; j++)
                #pragma unroll
                for (int q = 0; q < 4; q++) C[b][j][q] = 0.0f;

        #pragma unroll
        for (int k = 0; k < 4; k++)
            #pragma unroll
            for (int j = 0; j < 8; j++) {
                uint32_t B[4];
                ldsm_x4t(B, sb + SW0 + bw_off + k * (16 * WSTR) + j * 32);
                mma16816(C[0][2 * j],     A[0][k], B[0], B[1]);
                mma16816(C[0][2 * j + 1], A[0][k], B[2], B[3]);
                mma16816(C[1][2 * j],     A[1][k], B[0], B[1]);
                mma16816(C[1][2 * j + 1], A[1][k], B[2], B[3]);
            }

        // ---- layers 1..4: register-chained, B reused across both blocks ----
        const uint32_t WS[4] = {SW1, SW2, SW3, SW4};
        #pragma unroll
        for (int l = 0; l < 4; l++) {
            #pragma unroll
            for (int b = 0; b < 2; b++)
                #pragma unroll
                for (int j = 0; j < 8; j++) {
                    A[b][j][0] = relu_pack(C[b][2 * j][0],     C[b][2 * j][1]);
                    A[b][j][1] = relu_pack(C[b][2 * j][2],     C[b][2 * j][3]);
                    A[b][j][2] = relu_pack(C[b][2 * j + 1][0], C[b][2 * j + 1][1]);
                    A[b][j][3] = relu_pack(C[b][2 * j + 1][2], C[b][2 * j + 1][3]);
                }
            #pragma unroll
            for (int b = 0; b < 2; b++)
                #pragma unroll
                for (int j = 0; j < 16; j++)
                    #pragma unroll
                    for (int q = 0; q < 4; q++) C[b][j][q] = 0.0f;

            #pragma unroll
            for (int k = 0; k < 8; k++)
                #pragma unroll
                for (int j = 0; j < 8; j++) {
                    uint32_t B[4];
                    ldsm_x4t(B, sb + WS[l] + bw_off + k * (16 * WSTR) + j * 32);
                    mma16816(C[0][2 * j],     A[0][k], B[0], B[1]);
                    mma16816(C[0][2 * j + 1], A[0][k], B[2], B[3]);
                    mma16816(C[1][2 * j],     A[1][k], B[0], B[1]);
                    mma16816(C[1][2 * j + 1], A[1][k], B[2], B[3]);
                }
        }

        // ---- layer 5: [16x128] @ W5[128x16], both blocks ----
        #pragma unroll
        for (int b = 0; b < 2; b++)
            #pragma unroll
            for (int j = 0; j < 8; j++) {
                A[b][j][0] = relu_pack(C[b][2 * j][0],     C[b][2 * j][1]);
                A[b][j][1] = relu_pack(C[b][2 * j][2],     C[b][2 * j][3]);
                A[b][j][2] = relu_pack(C[b][2 * j + 1][0], C[b][2 * j + 1][1]);
                A[b][j][3] = relu_pack(C[b][2 * j + 1][2], C[b][2 * j + 1][3]);
            }
        float C2[2][2][4];
        #pragma unroll
        for (int b = 0; b < 2; b++)
            #pragma unroll
            for (int j = 0; j < 2; j++)
                #pragma unroll
                for (int q = 0; q < 4; q++) C2[b][j][q] = 0.0f;

        #pragma unroll
        for (int k = 0; k < 8; k++) {
            uint32_t B[4];
            ldsm_x4t(B, sb + SW5 + b5_off + k * (16 * W5STR));
            mma16816(C2[0][0], A[0][k], B[0], B[1]);
            mma16816(C2[0][1], A[0][k], B[2], B[3]);
            mma16816(C2[1][0], A[1][k], B[0], B[1]);
            mma16816(C2[1][1], A[1][k], B[2], B[3]);
        }

        // ---- store: + bias, fp32 ----
        const int row0 = lane >> 2;
        #pragma unroll
        for (int b = 0; b < 2; b++) {
            const size_t g0 = ((size_t)t * MTILE + 32 * wid + 16 * b + row0) * DIMO;
            const size_t g1 = g0 + 8 * DIMO;
            float2 v;
            v.x = C2[b][0][0] + bz0; v.y = C2[b][0][1] + bz1;
            *(float2*)(out + g0 + col0) = v;
            v.x = C2[b][1][0] + bz2; v.y = C2[b][1][1] + bz3;
            *(float2*)(out + g0 + 8 + col0) = v;
            v.x = C2[b][0][2] + bz0; v.y = C2[b][0][3] + bz1;
            *(float2*)(out + g1 + col0) = v;
            v.x = C2[b][1][2] + bz2; v.y = C2[b][1][3] + bz3;
            *(float2*)(out + g1 + 8 + col0) = v;
        }

        __syncthreads();   // x tile free for next iteration
    }
}

// ---------------- launch ----------------
extern "C" void kernel_launch(void* const* d_in, const int* in_sizes, int n_in,
                              void* d_out, int out_size) {
    const float* x    = (const float*)d_in[0];
    const float* W0   = (const float*)d_in[1];
    const float* W1   = (const float*)d_in[2];
    const float* W2   = (const float*)d_in[3];
    const float* W3   = (const float*)d_in[4];
    const float* W4   = (const float*)d_in[5];
    const float* W5   = (const float*)d_in[6];
    const float* bias = (const float*)d_in[7];
    float* out = (float*)d_out;

    cudaFuncSetAttribute(mlp_hmma_kernel,
                         cudaFuncAttributeMaxDynamicSharedMemorySize, SMEM_TOTAL);
    int sm = 148;
    cudaDeviceGetAttribute(&sm, cudaDevAttrMultiProcessorCount, 0);
    int grid = sm < NTILES ? sm : NTILES;
    mlp_hmma_kernel<<<grid, NTHREADS, SMEM_TOTAL>>>(x, W0, W1, W2, W3, W4, W5,
                                                    bias, out);
}

// round 5
// speedup vs baseline: 1.0197x; 1.0114x over previous
#include <cuda_runtime.h>
#include <cuda_fp16.h>
#include <cstdint>

// ---------------- problem constants ----------------
#define NSAMP   524288
#define MTILE   256
#define NTILES  (NSAMP / MTILE)   // 2048
#define NTHREADS 512
#define DIMO    16

// ---------------- SMEM layout (bytes) ----------------
// Weights: K-major [k rows x n cols] fp16, 256B row stride (hidden), XOR-swizzled
//          16B chunks: chunk' = (c&8) | ((c ^ (k&7)) & 7)   -> ldsm phase conflict-free
// W5: 48B row stride (16 cols + 8 pad), no swizzle (48-stride spreads banks)
// Act: [256 rows x 136 halfs] = 272B stride (padded, conflict-free ldsm/STS)
#define SW0   0
#define SW1   16384
#define SW2   49152
#define SW3   81920
#define SW4   114688
#define SW5   147456
#define SACT  153600
#define ACTSTR 272
#define SMEM_TOTAL (SACT + 256 * ACTSTR)   // 223232

// ---------------- PTX helpers (plain-sm_103-legal) ----------------
__device__ __forceinline__ uint32_t smem_u32(const void* p) {
    uint32_t a;
    asm("{ .reg .u64 t; cvta.to.shared.u64 t, %1; cvt.u32.u64 %0, t; }"
        : "=r"(a) : "l"(p));
    return a;
}
__device__ __forceinline__ void ldsm_x4(uint32_t* r, uint32_t addr) {
    asm volatile("ldmatrix.sync.aligned.m8n8.x4.shared.b16 {%0,%1,%2,%3}, [%4];"
                 : "=r"(r[0]), "=r"(r[1]), "=r"(r[2]), "=r"(r[3]) : "r"(addr));
}
__device__ __forceinline__ void ldsm_x4t(uint32_t* r, uint32_t addr) {
    asm volatile("ldmatrix.sync.aligned.m8n8.x4.trans.shared.b16 {%0,%1,%2,%3}, [%4];"
                 : "=r"(r[0]), "=r"(r[1]), "=r"(r[2]), "=r"(r[3]) : "r"(addr));
}
__device__ __forceinline__ void mma16816(float* c, const uint32_t* a,
                                         uint32_t b0, uint32_t b1) {
    asm volatile(
        "mma.sync.aligned.m16n8k16.row.col.f32.f16.f16.f32 "
        "{%0,%1,%2,%3}, {%4,%5,%6,%7}, {%8,%9}, {%0,%1,%2,%3};"
        : "+f"(c[0]), "+f"(c[1]), "+f"(c[2]), "+f"(c[3])
        : "r"(a[0]), "r"(a[1]), "r"(a[2]), "r"(a[3]), "r"(b0), "r"(b1));
}
__device__ __forceinline__ uint32_t relu_pack(float a, float b) {
    __half2 h = __floats2half2_rn(fmaxf(a, 0.0f), fmaxf(b, 0.0f));
    return *(uint32_t*)&h;
}
#define PAIR_BAR() asm volatile("bar.sync %0, 64;" :: "r"(barid) : "memory")

// one k-block of one hidden-type layer: 4 ldsm.x4t B loads, 16 MMAs
__device__ __forceinline__ void do_kb(float C[2][8][4],
                                      const uint32_t* A0, const uint32_t* A1,
                                      uint32_t wkb_addr, const uint32_t* bB) {
    #pragma unroll
    for (int c2 = 0; c2 < 4; c2++) {
        uint32_t B[4];
        ldsm_x4t(B, wkb_addr + bB[c2]);
        mma16816(C[0][2 * c2],     A0, B[0], B[1]);
        mma16816(C[0][2 * c2 + 1], A0, B[2], B[3]);
        mma16816(C[1][2 * c2],     A1, B[0], B[1]);
        mma16816(C[1][2 * c2 + 1], A1, B[2], B[3]);
    }
}

// ---------------- kernel ----------------
__global__ void __launch_bounds__(NTHREADS, 1)
mlp_pair_kernel(const float* __restrict__ x,
                const float* __restrict__ gW0, const float* __restrict__ gW1,
                const float* __restrict__ gW2, const float* __restrict__ gW3,
                const float* __restrict__ gW4, const float* __restrict__ gW5,
                const float* __restrict__ bias,
                float* __restrict__ out) {
    extern __shared__ char smem[];
    const uint32_t sb = smem_u32(smem);
    const int tid  = threadIdx.x;
    const int wid  = tid >> 5;
    const int lane = tid & 31;
    const int pair = wid & 7;          // 8 pairs
    const int h    = wid >> 3;         // 0 = N[0,64), 1 = N[64,128)
    const int barid = pair + 1;

    // ---- one-time: weights -> fp16 SMEM, swizzled K-major ----
    // hidden weights (k rows x 128 cols): addr = k*256 + swc*16 + (n4&1)*8
    {
        const float* gws[5] = {gW0, gW1, gW2, gW3, gW4};
        const uint32_t so[5] = {SW0, SW1, SW2, SW3, SW4};
        const int rows[5] = {64, 128, 128, 128, 128};
        #pragma unroll
        for (int w = 0; w < 5; w++) {
            for (int i = tid; i < rows[w] * 32; i += NTHREADS) {
                int k = i >> 5, n4 = i & 31;
                float4 v = ((const float4*)gws[w])[i];
                __half2 h0 = __floats2half2_rn(v.x, v.y), h1 = __floats2half2_rn(v.z, v.w);
                uint2 p = make_uint2(*(uint32_t*)&h0, *(uint32_t*)&h1);
                int c = n4 >> 1;
                int swc = (c & 8) | ((c ^ (k & 7)) & 7);
                *(uint2*)(smem + so[w] + k * 256 + swc * 16 + (n4 & 1) * 8) = p;
            }
        }
    }
    for (int i = tid; i < 128 * 4; i += NTHREADS) {   // W5 128x16, 48B stride
        int k = i >> 2, n4 = i & 3;
        float4 v = ((const float4*)gW5)[i];
        __half2 h0 = __floats2half2_rn(v.x, v.y), h1 = __floats2half2_rn(v.z, v.w);
        uint2 p = make_uint2(*(uint32_t*)&h0, *(uint32_t*)&h1);
        *(uint2*)(smem + SW5 + k * 48 + n4 * 8) = p;
    }

    const int col0 = (lane & 3) * 2;
    const int row0 = lane >> 2;
    float bz0 = __ldg(bias + col0);
    float bz1 = __ldg(bias + col0 + 1);
    float bz2 = __ldg(bias + 8 + col0);
    float bz3 = __ldg(bias + 9 + col0);

    __syncthreads();

    // ---- per-lane address bases ----
    const int lrow = lane & 15;
    const int lhi  = lane >> 4;
    // act A-stream base: fragment (mb,kb) at aA + mb*4352 + kb*32
    const uint32_t aA = sb + SACT + (32 * pair + lrow) * ACTSTR + lhi * 16;
    // act STS base (own C half): (mb,i) chunk at sts0 + mb*4352 + i*32 (+8*272,+16)
    const uint32_t sts0 = sb + SACT + (32 * pair + row0) * ACTSTR
                        + (h * 64 + col0) * 2;
    // B lane offsets for the 4 c2 chunks of own N-half (hidden layers)
    uint32_t bB[4];
    #pragma unroll
    for (int c2 = 0; c2 < 4; c2++) {
        int c = 8 * h + 2 * c2 + lhi;
        int swc = (c & 8) | ((c ^ (lrow & 7)) & 7);
        bB[c2] = (uint32_t)lrow * 256 + swc * 16;
    }
    const uint32_t b5 = (uint32_t)lrow * 48 + lhi * 16;   // W5 lane offset
    const int lt = h * 32 + lane;                          // 0..63 within pair

    for (int t = blockIdx.x; t < NTILES; t += gridDim.x) {
        // ---- x: pair loads its 32 rows x 64 cols fp32 -> fp16 act[0..64) ----
        const float4* xg = (const float4*)(x + ((size_t)t * MTILE + 32 * pair) * 64);
        #pragma unroll
        for (int it = 0; it < 8; it++) {
            int idx = lt + it * 64;
            int r = idx >> 4, c4 = idx & 15;
            float4 v = xg[idx];
            __half2 h0 = __floats2half2_rn(v.x, v.y), h1 = __floats2half2_rn(v.z, v.w);
            uint2 p = make_uint2(*(uint32_t*)&h0, *(uint32_t*)&h1);
            *(uint2*)(smem + SACT + (32 * pair + r) * ACTSTR + c4 * 8) = p;
        }
        PAIR_BAR();

        float C[2][8][4];
        #pragma unroll
        for (int b = 0; b < 2; b++)
            #pragma unroll
            for (int j = 0; j < 8; j++)
                #pragma unroll
                for (int q = 0; q < 4; q++) C[b][j][q] = 0.0f;

        // ---- layer 0: K=64, A streamed from x region ----
        #pragma unroll
        for (int kb = 0; kb < 4; kb++) {
            uint32_t As0[4], As1[4];
            ldsm_x4(As0, aA + kb * 32);
            ldsm_x4(As1, aA + 4352 + kb * 32);
            do_kb(C, As0, As1, sb + SW0 + kb * 4096, bB);
        }

        // ---- layers 1..4: own half register-chained, partner half via SMEM ----
        uint32_t Aown[2][4][4];
        const uint32_t WS[4] = {SW1, SW2, SW3, SW4};
        #pragma unroll
        for (int l = 0; l < 4; l++) {
            #pragma unroll
            for (int mb = 0; mb < 2; mb++)
                #pragma unroll
                for (int i = 0; i < 4; i++) {
                    Aown[mb][i][0] = relu_pack(C[mb][2 * i][0],     C[mb][2 * i][1]);
                    Aown[mb][i][1] = relu_pack(C[mb][2 * i][2],     C[mb][2 * i][3]);
                    Aown[mb][i][2] = relu_pack(C[mb][2 * i + 1][0], C[mb][2 * i + 1][1]);
                    Aown[mb][i][3] = relu_pack(C[mb][2 * i + 1][2], C[mb][2 * i + 1][3]);
                }
            PAIR_BAR();   // partner done reading previous act contents
            #pragma unroll
            for (int mb = 0; mb < 2; mb++)
                #pragma unroll
                for (int i = 0; i < 4; i++) {
                    uint32_t a = sts0 + mb * 4352 + i * 32;
                    *(uint32_t*)(smem + (a - sb))            = Aown[mb][i][0];
                    *(uint32_t*)(smem + (a - sb) + 8 * 272)  = Aown[mb][i][1];
                    *(uint32_t*)(smem + (a - sb) + 16)       = Aown[mb][i][2];
                    *(uint32_t*)(smem + (a - sb) + 8 * 272 + 16) = Aown[mb][i][3];
                }
            #pragma unroll
            for (int b = 0; b < 2; b++)
                #pragma unroll
                for (int j = 0; j < 8; j++)
                    #pragma unroll
                    for (int q = 0; q < 4; q++) C[b][j][q] = 0.0f;
            PAIR_BAR();   // act halves visible

            const uint32_t wb = sb + WS[l];
            #pragma unroll
            for (int i = 0; i < 4; i++) {          // own k-blocks (registers)
                int kb = 4 * h + i;
                do_kb(C, Aown[0][i], Aown[1][i], wb + kb * 4096, bB);
            }
            #pragma unroll
            for (int i = 0; i < 4; i++) {          // partner k-blocks (SMEM)
                int kb = 4 * (1 - h) + i;
                uint32_t As0[4], As1[4];
                ldsm_x4(As0, aA + kb * 32);
                ldsm_x4(As1, aA + 4352 + kb * 32);
                do_kb(C, As0, As1, wb + kb * 4096, bB);
            }
        }

        // ---- layer 5: N=16 (both warps compute, split store by m-block) ----
        #pragma unroll
        for (int mb = 0; mb < 2; mb++)
            #pragma unroll
            for (int i = 0; i < 4; i++) {
                Aown[mb][i][0] = relu_pack(C[mb][2 * i][0],     C[mb][2 * i][1]);
                Aown[mb][i][1] = relu_pack(C[mb][2 * i][2],     C[mb][2 * i][3]);
                Aown[mb][i][2] = relu_pack(C[mb][2 * i + 1][0], C[mb][2 * i + 1][1]);
                Aown[mb][i][3] = relu_pack(C[mb][2 * i + 1][2], C[mb][2 * i + 1][3]);
            }
        PAIR_BAR();
        #pragma unroll
        for (int mb = 0; mb < 2; mb++)
            #pragma unroll
            for (int i = 0; i < 4; i++) {
                uint32_t a = sts0 + mb * 4352 + i * 32;
                *(uint32_t*)(smem + (a - sb))            = Aown[mb][i][0];
                *(uint32_t*)(smem + (a - sb) + 8 * 272)  = Aown[mb][i][1];
                *(uint32_t*)(smem + (a - sb) + 16)       = Aown[mb][i][2];
                *(uint32_t*)(smem + (a - sb) + 8 * 272 + 16) = Aown[mb][i][3];
            }
        PAIR_BAR();

        float C5[2][2][4];
        #pragma unroll
        for (int b = 0; b < 2; b++)
            #pragma unroll
            for (int j = 0; j < 2; j++)
                #pragma unroll
                for (int q = 0; q < 4; q++) C5[b][j][q] = 0.0f;

        #pragma unroll
        for (int i = 0; i < 4; i++) {              // own k-blocks
            int kb = 4 * h + i;
            uint32_t B[4];
            ldsm_x4t(B, sb + SW5 + b5 + kb * 768);
            mma16816(C5[0][0], Aown[0][i], B[0], B[1]);
            mma16816(C5[0][1], Aown[0][i], B[2], B[3]);
            mma16816(C5[1][0], Aown[1][i], B[0], B[1]);
            mma16816(C5[1][1], Aown[1][i], B[2], B[3]);
        }
        #pragma unroll
        for (int i = 0; i < 4; i++) {              // partner k-blocks
            int kb = 4 * (1 - h) + i;
            uint32_t As0[4], As1[4];
            ldsm_x4(As0, aA + kb * 32);
            ldsm_x4(As1, aA + 4352 + kb * 32);
            uint32_t B[4];
            ldsm_x4t(B, sb + SW5 + b5 + kb * 768);
            mma16816(C5[0][0], As0, B[0], B[1]);
            mma16816(C5[0][1], As0, B[2], B[3]);
            mma16816(C5[1][0], As1, B[0], B[1]);
            mma16816(C5[1][1], As1, B[2], B[3]);
        }
        PAIR_BAR();   // all act reads done -> next tile may overwrite

        // store m-block == h rows
        const size_t g0 = ((size_t)t * MTILE + 32 * pair + 16 * h + row0) * DIMO;
        const size_t g1 = g0 + 8 * DIMO;
        float2 v;
        v.x = C5[h][0][0] + bz0; v.y = C5[h][0][1] + bz1;
        *(float2*)(out + g0 + col0) = v;
        v.x = C5[h][1][0] + bz2; v.y = C5[h][1][1] + bz3;
        *(float2*)(out + g0 + 8 + col0) = v;
        v.x = C5[h][0][2] + bz0; v.y = C5[h][0][3] + bz1;
        *(float2*)(out + g1 + col0) = v;
        v.x = C5[h][1][2] + bz2; v.y = C5[h][1][3] + bz3;
        *(float2*)(out + g1 + 8 + col0) = v;
    }
}

// ---------------- launch ----------------
extern "C" void kernel_launch(void* const* d_in, const int* in_sizes, int n_in,
                              void* d_out, int out_size) {
    const float* x    = (const float*)d_in[0];
    const float* W0   = (const float*)d_in[1];
    const float* W1   = (const float*)d_in[2];
    const float* W2   = (const float*)d_in[3];
    const float* W3   = (const float*)d_in[4];
    const float* W4   = (const float*)d_in[5];
    const float* W5   = (const float*)d_in[6];
    const float* bias = (const float*)d_in[7];
    float* out = (float*)d_out;

    cudaFuncSetAttribute(mlp_pair_kernel,
                         cudaFuncAttributeMaxDynamicSharedMemorySize, SMEM_TOTAL);
    int sm = 148;
    cudaDeviceGetAttribute(&sm, cudaDevAttrMultiProcessorCount, 0);
    int grid = sm < NTILES ? sm : NTILES;
    mlp_pair_kernel<<<grid, NTHREADS, SMEM_TOTAL>>>(x, W0, W1, W2, W3, W4, W5,
                                                    bias, out);
}

// round 6
// speedup vs baseline: 1.0724x; 1.0516x over previous
#include <cuda_runtime.h>
#include <cuda_fp16.h>
#include <cstdint>

// ---------------- problem constants ----------------
#define NSAMP   524288
#define MTILE   256
#define NTILES  (NSAMP / MTILE)   // 2048
#define NTHREADS 512
#define DIMO    16

// ---------------- SMEM layout (bytes) ----------------
// Hidden weights: K-major [k rows x 128 cols] fp16, 256B row stride, XOR-swizzled
//   16B chunks: swc = (c&8) | ((c ^ (k&7)) & 7)  -> ldsm phase conflict-free
// W5: 48B row stride (16 cols + 8 pad), no swizzle
// x: [256 rows x 72 halfs] = 144B stride (conflict-free ldsm/STS), per-warp private rows
#define SW0   0
#define SW1   16384
#define SW2   49152
#define SW3   81920
#define SW4   114688
#define SW5   147456
#define SX    153600
#define XSTR  144
#define SMEM_TOTAL (SX + 256 * XSTR)   // 190464

// ---------------- PTX helpers (plain-sm_103-legal) ----------------
__device__ __forceinline__ uint32_t smem_u32(const void* p) {
    uint32_t a;
    asm("{ .reg .u64 t; cvta.to.shared.u64 t, %1; cvt.u32.u64 %0, t; }"
        : "=r"(a) : "l"(p));
    return a;
}
__device__ __forceinline__ void ldsm_x4(uint32_t* r, uint32_t addr) {
    asm volatile("ldmatrix.sync.aligned.m8n8.x4.shared.b16 {%0,%1,%2,%3}, [%4];"
                 : "=r"(r[0]), "=r"(r[1]), "=r"(r[2]), "=r"(r[3]) : "r"(addr));
}
__device__ __forceinline__ void ldsm_x4t(uint32_t* r, uint32_t addr) {
    asm volatile("ldmatrix.sync.aligned.m8n8.x4.trans.shared.b16 {%0,%1,%2,%3}, [%4];"
                 : "=r"(r[0]), "=r"(r[1]), "=r"(r[2]), "=r"(r[3]) : "r"(addr));
}
__device__ __forceinline__ void mma16816(float* c, const uint32_t* a,
                                         uint32_t b0, uint32_t b1) {
    asm volatile(
        "mma.sync.aligned.m16n8k16.row.col.f32.f16.f16.f32 "
        "{%0,%1,%2,%3}, {%4,%5,%6,%7}, {%8,%9}, {%0,%1,%2,%3};"
        : "+f"(c[0]), "+f"(c[1]), "+f"(c[2]), "+f"(c[3])
        : "r"(a[0]), "r"(a[1]), "r"(a[2]), "r"(a[3]), "r"(b0), "r"(b1));
}
__device__ __forceinline__ uint32_t relu_pack(float a, float b) {
    __half2 h = __floats2half2_rn(fmaxf(a, 0.0f), fmaxf(b, 0.0f));
    return *(uint32_t*)&h;
}

// ---------------- kernel ----------------
__global__ void __launch_bounds__(NTHREADS, 1)
mlp_chain_kernel(const float* __restrict__ x,
                 const float* __restrict__ gW0, const float* __restrict__ gW1,
                 const float* __restrict__ gW2, const float* __restrict__ gW3,
                 const float* __restrict__ gW4, const float* __restrict__ gW5,
                 const float* __restrict__ bias,
                 float* __restrict__ out) {
    extern __shared__ char smem[];
    const uint32_t sb = smem_u32(smem);
    const int tid  = threadIdx.x;
    const int wid  = tid >> 5;
    const int lane = tid & 31;

    // ---- one-time: weights -> fp16 SMEM, swizzled K-major ----
    {
        const float* gws[5] = {gW0, gW1, gW2, gW3, gW4};
        const uint32_t so[5] = {SW0, SW1, SW2, SW3, SW4};
        const int rows[5] = {64, 128, 128, 128, 128};
        #pragma unroll
        for (int w = 0; w < 5; w++) {
            for (int i = tid; i < rows[w] * 32; i += NTHREADS) {
                int k = i >> 5, n4 = i & 31;
                float4 v = ((const float4*)gws[w])[i];
                __half2 h0 = __floats2half2_rn(v.x, v.y), h1 = __floats2half2_rn(v.z, v.w);
                uint2 p = make_uint2(*(uint32_t*)&h0, *(uint32_t*)&h1);
                int c = n4 >> 1;
                int swc = (c & 8) | ((c ^ (k & 7)) & 7);
                *(uint2*)(smem + so[w] + k * 256 + swc * 16 + (n4 & 1) * 8) = p;
            }
        }
    }
    for (int i = tid; i < 128 * 4; i += NTHREADS) {   // W5 128x16, 48B stride
        int k = i >> 2, n4 = i & 3;
        float4 v = ((const float4*)gW5)[i];
        __half2 h0 = __floats2half2_rn(v.x, v.y), h1 = __floats2half2_rn(v.z, v.w);
        uint2 p = make_uint2(*(uint32_t*)&h0, *(uint32_t*)&h1);
        *(uint2*)(smem + SW5 + k * 48 + n4 * 8) = p;
    }

    const int col0 = (lane & 3) * 2;
    const int row0 = lane >> 2;
    float bz0 = __ldg(bias + col0);
    float bz1 = __ldg(bias + col0 + 1);
    float bz2 = __ldg(bias + 8 + col0);
    float bz3 = __ldg(bias + 9 + col0);

    __syncthreads();   // only block-wide sync in the kernel

    // ---- per-lane bases ----
    const int lrow = lane & 15;
    const int lhi  = lane >> 4;
    const uint32_t lr256 = (uint32_t)lrow * 256;
    const int lr7 = lrow & 7;
    const uint32_t aA = sb + SX + (16 * wid + lrow) * XSTR + lhi * 16;
    const uint32_t w5a = sb + SW5 + (uint32_t)lrow * 48 + lhi * 16;
    const uint32_t xsts_row = SX + 16 * wid * XSTR;   // + r*144 + c4*8

    const int G = gridDim.x;

    // ---- prologue: load x tile for t = blockIdx.x ----
    {
        const float4* xg = (const float4*)(x + (size_t)blockIdx.x * MTILE * 64)
                         + wid * 256;
        #pragma unroll
        for (int it = 0; it < 8; it++) {
            int idx = lane + it * 32;
            int r = idx >> 4, c4 = idx & 15;
            float4 v = xg[idx];
            __half2 h0 = __floats2half2_rn(v.x, v.y), h1 = __floats2half2_rn(v.z, v.w);
            uint2 p = make_uint2(*(uint32_t*)&h0, *(uint32_t*)&h1);
            *(uint2*)(smem + xsts_row + r * XSTR + c4 * 8) = p;
        }
    }

    for (int t = blockIdx.x; t < NTILES; t += G) {
        __syncwarp();   // make own-warp STS (prologue / prefetch) ldsm-visible

        // ---- A fragments for layer 0 (x region free afterwards) ----
        uint32_t A[8][4];
        #pragma unroll
        for (int kb = 0; kb < 4; kb++) ldsm_x4(A[kb], aA + kb * 32);

        float C[16][4];
        #pragma unroll
        for (int j = 0; j < 16; j++)
            #pragma unroll
            for (int q = 0; q < 4; q++) C[j][q] = 0.0f;

        // ---- layer 0: K=64 ----
        {
            uint32_t wbj[8];
            #pragma unroll
            for (int j = 0; j < 8; j++) {
                int c = 2 * j + lhi;
                int swc = (c & 8) | ((c ^ lr7) & 7);
                wbj[j] = sb + SW0 + lr256 + swc * 16;
            }
            #pragma unroll
            for (int kb = 0; kb < 4; kb++)
                #pragma unroll
                for (int j = 0; j < 8; j++) {
                    uint32_t B[4];
                    ldsm_x4t(B, wbj[j] + kb * 4096);
                    mma16816(C[2 * j],     A[kb], B[0], B[1]);
                    mma16816(C[2 * j + 1], A[kb], B[2], B[3]);
                }
        }

        // ---- prefetch next x tile, half 0 (issue) ----
        const int tn = t + G;
        const bool pf = tn < NTILES;
        const float4* xgn = (const float4*)(x + (size_t)tn * MTILE * 64) + wid * 256;
        float4 vb[4];
        if (pf) {
            #pragma unroll
            for (int it = 0; it < 4; it++) vb[it] = xgn[lane + it * 32];
        }

        // ---- layers 1..4: fully register-chained ----
        const uint32_t WS[4] = {SW1, SW2, SW3, SW4};
        #pragma unroll
        for (int l = 0; l < 4; l++) {
            #pragma unroll
            for (int j = 0; j < 8; j++) {
                A[j][0] = relu_pack(C[2 * j][0],     C[2 * j][1]);
                A[j][1] = relu_pack(C[2 * j][2],     C[2 * j][3]);
                A[j][2] = relu_pack(C[2 * j + 1][0], C[2 * j + 1][1]);
                A[j][3] = relu_pack(C[2 * j + 1][2], C[2 * j + 1][3]);
            }
            #pragma unroll
            for (int j = 0; j < 16; j++)
                #pragma unroll
                for (int q = 0; q < 4; q++) C[j][q] = 0.0f;

            uint32_t wbj[8];
            #pragma unroll
            for (int j = 0; j < 8; j++) {
                int c = 2 * j + lhi;
                int swc = (c & 8) | ((c ^ lr7) & 7);
                wbj[j] = sb + WS[l] + lr256 + swc * 16;
            }
            #pragma unroll
            for (int kb = 0; kb < 8; kb++)
                #pragma unroll
                for (int j = 0; j < 8; j++) {
                    uint32_t B[4];
                    ldsm_x4t(B, wbj[j] + kb * 4096);
                    mma16816(C[2 * j],     A[kb], B[0], B[1]);
                    mma16816(C[2 * j + 1], A[kb], B[2], B[3]);
                }

            // drain prefetch halves into the (now free) x region
            if (l == 0 && pf) {
                #pragma unroll
                for (int it = 0; it < 4; it++) {
                    int idx = lane + it * 32;
                    int r = idx >> 4, c4 = idx & 15;
                    __half2 h0 = __floats2half2_rn(vb[it].x, vb[it].y);
                    __half2 h1 = __floats2half2_rn(vb[it].z, vb[it].w);
                    uint2 p = make_uint2(*(uint32_t*)&h0, *(uint32_t*)&h1);
                    *(uint2*)(smem + xsts_row + r * XSTR + c4 * 8) = p;
                }
                #pragma unroll
                for (int it = 0; it < 4; it++) vb[it] = xgn[lane + (it + 4) * 32];
            }
            if (l == 1 && pf) {
                #pragma unroll
                for (int it = 0; it < 4; it++) {
                    int idx = lane + (it + 4) * 32;
                    int r = idx >> 4, c4 = idx & 15;
                    __half2 h0 = __floats2half2_rn(vb[it].x, vb[it].y);
                    __half2 h1 = __floats2half2_rn(vb[it].z, vb[it].w);
                    uint2 p = make_uint2(*(uint32_t*)&h0, *(uint32_t*)&h1);
                    *(uint2*)(smem + xsts_row + r * XSTR + c4 * 8) = p;
                }
            }
        }

        // ---- layer 5: N=16 ----
        #pragma unroll
        for (int j = 0; j < 8; j++) {
            A[j][0] = relu_pack(C[2 * j][0],     C[2 * j][1]);
            A[j][1] = relu_pack(C[2 * j][2],     C[2 * j][3]);
            A[j][2] = relu_pack(C[2 * j + 1][0], C[2 * j + 1][1]);
            A[j][3] = relu_pack(C[2 * j + 1][2], C[2 * j + 1][3]);
        }
        float C5[2][4];
        #pragma unroll
        for (int j = 0; j < 2; j++)
            #pragma unroll
            for (int q = 0; q < 4; q++) C5[j][q] = 0.0f;

        #pragma unroll
        for (int kb = 0; kb < 8; kb++) {
            uint32_t B[4];
            ldsm_x4t(B, w5a + kb * 768);
            mma16816(C5[0], A[kb], B[0], B[1]);
            mma16816(C5[1], A[kb], B[2], B[3]);
        }

        // ---- store: + bias, fp32 ----
        const size_t g0 = ((size_t)t * MTILE + 16 * wid + row0) * DIMO;
        const size_t g1 = g0 + 8 * DIMO;
        float2 v;
        v.x = C5[0][0] + bz0; v.y = C5[0][1] + bz1;
        *(float2*)(out + g0 + col0) = v;
        v.x = C5[1][0] + bz2; v.y = C5[1][1] + bz3;
        *(float2*)(out + g0 + 8 + col0) = v;
        v.x = C5[0][2] + bz0; v.y = C5[0][3] + bz1;
        *(float2*)(out + g1 + col0) = v;
        v.x = C5[1][2] + bz2; v.y = C5[1][3] + bz3;
        *(float2*)(out + g1 + 8 + col0) = v;
    }
}

// ---------------- launch ----------------
extern "C" void kernel_launch(void* const* d_in, const int* in_sizes, int n_in,
                              void* d_out, int out_size) {
    const float* x    = (const float*)d_in[0];
    const float* W0   = (const float*)d_in[1];
    const float* W1   = (const float*)d_in[2];
    const float* W2   = (const float*)d_in[3];
    const float* W3   = (const float*)d_in[4];
    const float* W4   = (const float*)d_in[5];
    const float* W5   = (const float*)d_in[6];
    const float* bias = (const float*)d_in[7];
    float* out = (float*)d_out;

    cudaFuncSetAttribute(mlp_chain_kernel,
                         cudaFuncAttributeMaxDynamicSharedMemorySize, SMEM_TOTAL);
    int sm = 148;
    cudaDeviceGetAttribute(&sm, cudaDevAttrMultiProcessorCount, 0);
    int grid = sm < NTILES ? sm : NTILES;
    mlp_chain_kernel<<<grid, NTHREADS, SMEM_TOTAL>>>(x, W0, W1, W2, W3, W4, W5,
                                                     bias, out);
}